// round 12
// baseline (speedup 1.0000x reference)
#include <cuda_runtime.h>
#include <cstdint>

// out[src[e]*16 + k] += attrs[k*E + e]   (attrs is feature-major (F,E); attr_idx int32)
// Bound by LTS atomic-op throughput (16M RED.128). R10 shape (2 chunks of 8, occ~50%)
// + streaming evict-first loads so the 288MB read-once stream doesn't thrash the
// 6.4MB atomic-resident output in L2.

__device__ __forceinline__ void red_add_v4(float* addr, float a, float b, float c, float d)
{
    asm volatile("red.global.add.v4.f32 [%0], {%1, %2, %3, %4};"
                 :: "l"(addr), "f"(a), "f"(b), "f"(c), "f"(d)
                 : "memory");
}

__device__ __forceinline__ float4 ldcs_v4(const float4* p)
{
    float4 v;
    asm volatile("ld.global.cs.v4.f32 {%0, %1, %2, %3}, [%4];"
                 : "=f"(v.x), "=f"(v.y), "=f"(v.z), "=f"(v.w) : "l"(p));
    return v;
}

__device__ __forceinline__ int4 ldcs_i4(const int4* p)
{
    int4 v;
    asm volatile("ld.global.cs.v4.s32 {%0, %1, %2, %3}, [%4];"
                 : "=r"(v.x), "=r"(v.y), "=r"(v.z), "=r"(v.w) : "l"(p));
    return v;
}

// Eq = E/4 (edge quads). attrs4 laid out as (16, Eq) float4.
__global__ __launch_bounds__(256, 5)
void scatter_sum_f16_q4(const float4* __restrict__ attrs4,
                        const int4* __restrict__ src4,
                        float* __restrict__ out,
                        int Eq, int out_size)
{
    int q = blockIdx.x * blockDim.x + threadIdx.x;
    if (q >= Eq) return;

    int4 n4 = ldcs_i4(src4 + q);          // 4 consecutive src node ids (read-once)

    float* o0 = ((unsigned)n4.x * 16u + 16u <= (unsigned)out_size) ? out + (size_t)n4.x * 16 : nullptr;
    float* o1 = ((unsigned)n4.y * 16u + 16u <= (unsigned)out_size) ? out + (size_t)n4.y * 16 : nullptr;
    float* o2 = ((unsigned)n4.z * 16u + 16u <= (unsigned)out_size) ? out + (size_t)n4.z * 16 : nullptr;
    float* o3 = ((unsigned)n4.w * 16u + 16u <= (unsigned)out_size) ? out + (size_t)n4.w * 16 : nullptr;

    // ---- features 0..7 (8 LDG.128 in flight, then 8 RED.128) ----
    {
        float4 v[8];
        #pragma unroll
        for (int k = 0; k < 8; k++)
            v[k] = ldcs_v4(attrs4 + (size_t)k * Eq + q);

        if (o0) { red_add_v4(o0 + 0, v[0].x, v[1].x, v[2].x, v[3].x);
                  red_add_v4(o0 + 4, v[4].x, v[5].x, v[6].x, v[7].x); }
        if (o1) { red_add_v4(o1 + 0, v[0].y, v[1].y, v[2].y, v[3].y);
                  red_add_v4(o1 + 4, v[4].y, v[5].y, v[6].y, v[7].y); }
        if (o2) { red_add_v4(o2 + 0, v[0].z, v[1].z, v[2].z, v[3].z);
                  red_add_v4(o2 + 4, v[4].z, v[5].z, v[6].z, v[7].z); }
        if (o3) { red_add_v4(o3 + 0, v[0].w, v[1].w, v[2].w, v[3].w);
                  red_add_v4(o3 + 4, v[4].w, v[5].w, v[6].w, v[7].w); }
    }
    // ---- features 8..15 ----
    {
        float4 v[8];
        #pragma unroll
        for (int k = 0; k < 8; k++)
            v[k] = ldcs_v4(attrs4 + (size_t)(k + 8) * Eq + q);

        if (o0) { red_add_v4(o0 + 8,  v[0].x, v[1].x, v[2].x, v[3].x);
                  red_add_v4(o0 + 12, v[4].x, v[5].x, v[6].x, v[7].x); }
        if (o1) { red_add_v4(o1 + 8,  v[0].y, v[1].y, v[2].y, v[3].y);
                  red_add_v4(o1 + 12, v[4].y, v[5].y, v[6].y, v[7].y); }
        if (o2) { red_add_v4(o2 + 8,  v[0].z, v[1].z, v[2].z, v[3].z);
                  red_add_v4(o2 + 12, v[4].z, v[5].z, v[6].z, v[7].z); }
        if (o3) { red_add_v4(o3 + 8,  v[0].w, v[1].w, v[2].w, v[3].w);
                  red_add_v4(o3 + 12, v[4].w, v[5].w, v[6].w, v[7].w); }
    }
}

// Scalar fallback for F != 16 or E % 4 != 0.
__global__ void scatter_sum_scalar(const float* __restrict__ attrs,
                                   const int* __restrict__ src,
                                   float* __restrict__ out,
                                   int E, int F, int out_size)
{
    int e = blockIdx.x * blockDim.x + threadIdx.x;
    if (e >= E) return;
    int n = src[e];
    long long base = (long long)n * F;
    if (n < 0 || base + F > out_size) return;
    float* o = out + base;
    for (int k = 0; k < F; k++)
        atomicAdd(o + k, __ldg(attrs + (size_t)k * E + e));
}

extern "C" void kernel_launch(void* const* d_in, const int* in_sizes, int n_in,
                              void* d_out, int out_size)
{
    const float* attrs = (const float*)d_in[0];   // (E, F) buffer, used as (F, E)
    const int*   aidx  = (const int*)d_in[1];     // (2, E) int32; row 0 = src

    int E = in_sizes[1] / 2;
    int F = in_sizes[0] / E;

    float* out = (float*)d_out;

    cudaMemsetAsync(d_out, 0, (size_t)out_size * sizeof(float), 0);

    const int threads = 256;

    if (F == 16 && (E % 4) == 0) {
        int Eq = E / 4;
        int blocks = (Eq + threads - 1) / threads;
        scatter_sum_f16_q4<<<blocks, threads, 0, 0>>>(
            (const float4*)attrs, (const int4*)aidx, out, Eq, out_size);
    } else {
        int blocks = (E + threads - 1) / threads;
        scatter_sum_scalar<<<blocks, threads, 0, 0>>>(attrs, aidx, out, E, F, out_size);
    }
}